// round 11
// baseline (speedup 1.0000x reference)
#include <cuda_runtime.h>
#include <cuda_fp16.h>
#include <cuda_bf16.h>
#include <cstdint>

// ---------------- problem dims ----------------
#define B_SZ   1024
#define S_SZ   256
#define IN_SZ  8
#define H_SZ   512
#define F_SZ   96
#define G4     2048          // 4*H
#define KV     1024          // virtual K: [Ah | Ah] x [Wh | Wl]  (fp16 2-term split)
#define NCHUNK 16            // KV / 64
#define NCTA_N 16
#define NCTA_M 16            // M-tile = 64 rows -> 2 CTAs/SM (occupancy play)
#define MTILE  64

// ---------------- shared memory layout ----------------
// 4 stages x (A 8 KB + B 16 KB); epilogue reuses stage region as C (64x132 f32 = 33 KB)
#define STAGE_BYTES 24576
#define SM_BIAS   98304    // 128 floats
#define SM_WIH    98816    // 128*8 floats
#define SM_XS     102912   // 64*9 floats
#define SM_OUTW   105216   // 32 floats
#define SMEM_TOTAL 105344  // x2 CTAs = 210688 <= 228KB/SM

// ---------------- static device scratch (no runtime alloc) ----------------
__device__ __align__(1024) __half g_Wv[3][(size_t)G4 * KV];   // enc / dec0 / dec-folded
__device__ __align__(1024) __half g_A[2][(size_t)B_SZ * KV];  // ping-pong A_virt
__device__ __align__(1024) float g_Cst[B_SZ * H_SZ];          // cell state fp32
__device__ float g_bias[3][G4];                               // permuted fused biases
__device__ float g_WihP[G4 * IN_SZ];                          // permuted enc_Wih
__device__ float g_predP[F_SZ][NCTA_N][B_SZ];                 // per-nCTA pred partials

// ---------------- helpers ----------------
__device__ __forceinline__ uint32_t smem_u32(const void* p) {
    uint32_t a;
    asm("{ .reg .u64 t; cvta.to.shared.u64 t, %1; cvt.u32.u64 %0, t; }" : "=r"(a) : "l"(p));
    return a;
}
__device__ __forceinline__ void cp16(uint32_t saddr, const void* gptr) {
    asm volatile("cp.async.cg.shared.global [%0], [%1], 16;"
                 :: "r"(saddr), "l"(__cvta_generic_to_global(gptr)) : "memory");
}
#define CP_COMMIT() asm volatile("cp.async.commit_group;" ::: "memory")
#define CP_WAIT2()  asm volatile("cp.async.wait_group 2;" ::: "memory")
#define CP_WAIT0()  asm volatile("cp.async.wait_group 0;" ::: "memory")

__device__ __forceinline__ void ldm4(uint32_t& r0, uint32_t& r1, uint32_t& r2, uint32_t& r3,
                                     uint32_t addr) {
    asm volatile("ldmatrix.sync.aligned.m8n8.x4.shared.b16 {%0,%1,%2,%3}, [%4];"
                 : "=r"(r0), "=r"(r1), "=r"(r2), "=r"(r3) : "r"(addr));
}
__device__ __forceinline__ void mma16816(float* c, const uint32_t* a, const uint32_t* b) {
    asm volatile(
        "mma.sync.aligned.m16n8k16.row.col.f32.f16.f16.f32 "
        "{%0,%1,%2,%3}, {%4,%5,%6,%7}, {%8,%9}, {%0,%1,%2,%3};"
        : "+f"(c[0]), "+f"(c[1]), "+f"(c[2]), "+f"(c[3])
        : "r"(a[0]), "r"(a[1]), "r"(a[2]), "r"(a[3]), "r"(b[0]), "r"(b[1]));
}

// ---------------- prep: permute + fp16 hi/lo split weights, fold decoder feedback ----------------
// permuted col p = 4u + gate  <-  source row s = gate*512 + u  (PyTorch gate order i,f,g,o)
__global__ void prep_kernel(const float* __restrict__ encWhh, const float* __restrict__ decWhh,
                            const float* __restrict__ decWih, const float* __restrict__ outW,
                            const float* __restrict__ encBih, const float* __restrict__ encBhh,
                            const float* __restrict__ decBih, const float* __restrict__ decBhh,
                            const float* __restrict__ outB,   const float* __restrict__ encWih) {
    int idx = blockIdx.x * blockDim.x + threadIdx.x;
    if (idx < G4 * H_SZ) {
        int p = idx >> 9;
        int k = idx & 511;
        int s = ((p & 3) << 9) | (p >> 2);
        size_t o = (size_t)p * KV + k;

        float v0 = encWhh[s * H_SZ + k];
        __half h0 = __float2half_rn(v0);
        g_Wv[0][o] = h0; g_Wv[0][o + 512] = __float2half_rn(v0 - __half2float(h0));

        float v1 = decWhh[s * H_SZ + k];
        __half h1 = __float2half_rn(v1);
        g_Wv[1][o] = h1; g_Wv[1][o + 512] = __float2half_rn(v1 - __half2float(h1));

        float v2 = v1 + decWih[s] * outW[k];           // fold y-feedback into Whh
        __half h2 = __float2half_rn(v2);
        g_Wv[2][o] = h2; g_Wv[2][o + 512] = __float2half_rn(v2 - __half2float(h2));
    }
    if (idx < G4) {
        int p = idx;
        int s = ((p & 3) << 9) | (p >> 2);
        g_bias[0][p] = encBih[s] + encBhh[s];
        float db = decBih[s] + decBhh[s];
        g_bias[1][p] = db;
        g_bias[2][p] = db + outB[0] * decWih[s];       // fold outB feedback
#pragma unroll
        for (int j = 0; j < IN_SZ; j++) g_WihP[p * IN_SZ + j] = encWih[s * IN_SZ + j];
    }
}

__global__ void init_kernel() {
    int i = blockIdx.x * blockDim.x + threadIdx.x;
    int stride = gridDim.x * blockDim.x;
    uint32_t* a0 = reinterpret_cast<uint32_t*>(g_A[0]);
    for (int idx = i; idx < B_SZ * KV / 2; idx += stride) a0[idx] = 0u;
    for (int idx = i; idx < B_SZ * H_SZ; idx += stride) g_Cst[idx] = 0.f;
}

// ---------------- one LSTM time step ----------------
// C[64x128 tile] = A_virt[1024x1024] x B_virt[2048x1024]^T, then gate math locally.
// grid (16, 16): blockIdx.x = N-tile (128 permuted gate cols = 32 units), blockIdx.y = M-tile (64 rows).
// 512 threads = 16 warps arranged 2m x 4n x 2k; warp tile 32m x 32n; K-chunk halves
// reduced through smem at spill time. 2 CTAs resident per SM.
__global__ void __launch_bounds__(512, 2)
step_kernel(int wsel, int pb, int t_x, int td,
            const float* __restrict__ x, const float* __restrict__ outW) {
    extern __shared__ char smem[];
    const uint32_t sb = smem_u32(smem);
    const int tid = threadIdx.x;
    const int n0 = blockIdx.x, m0 = blockIdx.y;
    const bool has_x = (t_x >= 0);

    // ---- epilogue constants into their own smem region ----
    float* sm_bias = (float*)(smem + SM_BIAS);
    float* sm_wih  = (float*)(smem + SM_WIH);
    float* sm_xs   = (float*)(smem + SM_XS);
    float* sm_outw = (float*)(smem + SM_OUTW);
    if (tid < 128) sm_bias[tid] = g_bias[wsel][n0 * 128 + tid];
    if (tid < 32)  sm_outw[tid] = outW[n0 * 32 + tid];
    if (has_x) {
        int i = tid;
        if (i < MTILE * IN_SZ) {
            int r = i >> 3, j = i & 7;
            sm_xs[r * 9 + j] = x[((size_t)(m0 * MTILE + r) * S_SZ + t_x) * IN_SZ + j];
        }
        for (int i2 = tid; i2 < 128 * IN_SZ; i2 += 512) sm_wih[i2] = g_WihP[n0 * 128 * IN_SZ + i2];
    }

    const __half* __restrict__ gA = g_A[pb] + (size_t)m0 * MTILE * KV;
    const __half* __restrict__ gB = g_Wv[wsel] + (size_t)n0 * 128 * KV;

    // ---- stage loader: global -> XOR-swizzled smem via cp.async (512 threads) ----
    // A: 64 rows x 128 B (1 cp/thread); B: 128 rows x 128 B (2 cp/thread)
    auto load_stage = [&](int kc, int slot) {
        const uint32_t stA = sb + slot * STAGE_BYTES;
        const uint32_t stB = stA + 8192;
        const int c16 = tid & 7;
        const int rb = tid >> 3;          // 0..63
        {
            uint32_t so = (uint32_t)(rb * 128 + ((c16 ^ (rb & 7)) << 4));
            cp16(stA + so, gA + (size_t)rb * KV + kc * 64 + c16 * 8);
        }
#pragma unroll
        for (int it = 0; it < 2; it++) {
            int r = rb + it * 64;
            uint32_t so = (uint32_t)(r * 128 + ((c16 ^ (r & 7)) << 4));
            cp16(stB + so, gB + (size_t)r * KV + kc * 64 + c16 * 8);
        }
    };

    load_stage(0, 0); CP_COMMIT();
    load_stage(1, 1); CP_COMMIT();
    load_stage(2, 2); CP_COMMIT();

    const int lane = tid & 31, w = tid >> 5;
    const int wk = w & 1;                 // K-half of each chunk
    const int wn = (w >> 1) & 3;          // 4 n-columns of 32
    const int wm = w >> 3;                // 2 m-rows of 32
    const int lrow = lane & 15, lhalf = lane >> 4;

    float acc[2][4][4];
#pragma unroll
    for (int a = 0; a < 2; a++)
#pragma unroll
        for (int b = 0; b < 4; b++)
#pragma unroll
            for (int c = 0; c < 4; c++) acc[a][b][c] = 0.f;

    // ---- mainloop: 16 chunks of K=64, 4-stage cp.async pipeline, warp-level K-split ----
    for (int kc = 0; kc < NCHUNK; kc++) {
        CP_WAIT2();
        __syncthreads();
        const uint32_t stA = sb + (kc & 3) * STAGE_BYTES;
        const uint32_t stB = stA + 8192;
#pragma unroll
        for (int j = 0; j < 2; j++) {
            const int c16 = 2 * (wk * 2 + j) + lhalf;
            uint32_t af[2][4];
#pragma unroll
            for (int mt = 0; mt < 2; mt++) {
                int r = wm * 32 + mt * 16 + lrow;
                ldm4(af[mt][0], af[mt][1], af[mt][2], af[mt][3],
                     stA + r * 128 + ((c16 ^ (r & 7)) << 4));
            }
            uint32_t bfr[4][2];
#pragma unroll
            for (int nb = 0; nb < 2; nb++) {
                int r = wn * 32 + nb * 16 + lrow;
                uint32_t r0, r1, r2, r3;
                ldm4(r0, r1, r2, r3, stB + r * 128 + ((c16 ^ (r & 7)) << 4));
                bfr[nb * 2 + 0][0] = r0; bfr[nb * 2 + 0][1] = r2;
                bfr[nb * 2 + 1][0] = r1; bfr[nb * 2 + 1][1] = r3;
            }
#pragma unroll
            for (int mt = 0; mt < 2; mt++)
#pragma unroll
                for (int nt = 0; nt < 4; nt++)
                    mma16816(acc[mt][nt], af[mt], bfr[nt]);
        }
        if (kc + 3 < NCHUNK) load_stage(kc + 3, (kc + 3) & 3);
        CP_COMMIT();   // unconditional: keeps wait_group 2 semantics at the tail
    }
    CP_WAIT0();        // drain empty tail groups before smem reuse

    // ---- spill + K-half reduction into smem C tile (64 x 132, aligned float2) ----
    __syncthreads();
    float* Cs = reinterpret_cast<float*>(smem);
    if (wk == 0) {
#pragma unroll
        for (int mt = 0; mt < 2; mt++) {
#pragma unroll
            for (int nt = 0; nt < 4; nt++) {
                int r = wm * 32 + mt * 16 + (lane >> 2);
                int c = wn * 32 + nt * 8 + 2 * (lane & 3);
                Cs[r * 132 + c]           = acc[mt][nt][0];
                Cs[r * 132 + c + 1]       = acc[mt][nt][1];
                Cs[(r + 8) * 132 + c]     = acc[mt][nt][2];
                Cs[(r + 8) * 132 + c + 1] = acc[mt][nt][3];
            }
        }
    }
    __syncthreads();
    if (wk == 1) {
#pragma unroll
        for (int mt = 0; mt < 2; mt++) {
#pragma unroll
            for (int nt = 0; nt < 4; nt++) {
                int r = wm * 32 + mt * 16 + (lane >> 2);
                int c = wn * 32 + nt * 8 + 2 * (lane & 3);
                float2* p0 = reinterpret_cast<float2*>(&Cs[r * 132 + c]);
                float2 v0 = *p0; v0.x += acc[mt][nt][0]; v0.y += acc[mt][nt][1]; *p0 = v0;
                float2* p1 = reinterpret_cast<float2*>(&Cs[(r + 8) * 132 + c]);
                float2 v1 = *p1; v1.x += acc[mt][nt][2]; v1.y += acc[mt][nt][3]; *p1 = v1;
            }
        }
    }
    __syncthreads();

    // ---- gate pass: lane = local unit (cols 4u..4u+3 = i,f,g,o), 16 warps x 4 rows ----
    const int u = lane;
    const int ug = n0 * 32 + u;
    const float b_i = sm_bias[4 * u], b_f = sm_bias[4 * u + 1];
    const float b_g = sm_bias[4 * u + 2], b_o = sm_bias[4 * u + 3];
    const float ow = sm_outw[u];
    __half* __restrict__ hout = g_A[pb ^ 1];

#pragma unroll
    for (int i = 0; i < 4; i++) {
        int r = w + i * 16;
        int grow = m0 * MTILE + r;
        const float4 g4v = *reinterpret_cast<const float4*>(&Cs[r * 132 + 4 * u]);
        float gi = g4v.x + b_i, gf = g4v.y + b_f, gg = g4v.z + b_g, go = g4v.w + b_o;
        if (has_x) {
#pragma unroll
            for (int k = 0; k < 8; k++) {
                float xv = sm_xs[r * 9 + k];
                gi += xv * sm_wih[(4 * u + 0) * 8 + k];
                gf += xv * sm_wih[(4 * u + 1) * 8 + k];
                gg += xv * sm_wih[(4 * u + 2) * 8 + k];
                go += xv * sm_wih[(4 * u + 3) * 8 + k];
            }
        }
        float iv = 1.f / (1.f + expf(-gi));
        float fv = 1.f / (1.f + expf(-gf));
        float gv = tanhf(gg);
        float ov = 1.f / (1.f + expf(-go));
        size_t ci = (size_t)grow * H_SZ + ug;
        float cn = fv * g_Cst[ci] + iv * gv;
        g_Cst[ci] = cn;
        float hv = ov * tanhf(cn);
        __half hh = __float2half_rn(hv);
        __half* rowp = hout + (size_t)grow * KV;
        rowp[ug] = hh; rowp[512 + ug] = hh;            // A_virt = [Ah | Ah]
        if (td >= 0) {
            float p = hv * ow;
#pragma unroll
            for (int s = 16; s > 0; s >>= 1) p += __shfl_xor_sync(0xFFFFFFFFu, p, s);
            if (lane == 0) g_predP[td][n0][grow] = p;   // deterministic partial
        }
    }
}

// ---------------- output: out[b][f] = outB + sum_n predP[f][n][b] ----------------
__global__ void out_kernel(float* __restrict__ out, const float* __restrict__ outB) {
    int i = blockIdx.x * blockDim.x + threadIdx.x;
    if (i < B_SZ * F_SZ) {
        int b = i / F_SZ, f = i % F_SZ;
        float s = outB[0];
#pragma unroll
        for (int n = 0; n < NCTA_N; n++) s += g_predP[f][n][b];
        out[i] = s;
    }
}

// ---------------- launch ----------------
extern "C" void kernel_launch(void* const* d_in, const int* in_sizes, int n_in,
                              void* d_out, int out_size) {
    const float* x      = (const float*)d_in[0];
    const float* encWih = (const float*)d_in[1];
    const float* encWhh = (const float*)d_in[2];
    const float* encBih = (const float*)d_in[3];
    const float* encBhh = (const float*)d_in[4];
    const float* decWih = (const float*)d_in[5];
    const float* decWhh = (const float*)d_in[6];
    const float* decBih = (const float*)d_in[7];
    const float* decBhh = (const float*)d_in[8];
    const float* outW   = (const float*)d_in[9];
    const float* outB   = (const float*)d_in[10];

    cudaFuncSetAttribute(step_kernel, cudaFuncAttributeMaxDynamicSharedMemorySize, SMEM_TOTAL);

    init_kernel<<<512, 256>>>();
    prep_kernel<<<(G4 * H_SZ + 255) / 256, 256>>>(encWhh, decWhh, decWih, outW,
                                                  encBih, encBhh, decBih, decBhh, outB, encWih);
    dim3 grid(NCTA_N, NCTA_M);
    // encoder: 256 steps with x-term, weight set 0
    for (int t = 0; t < S_SZ; t++)
        step_kernel<<<grid, 512, SMEM_TOTAL>>>(0, t & 1, t, -1, x, outW);
    // decoder step 0: y0 = 0 -> plain dec weights (set 1)
    step_kernel<<<grid, 512, SMEM_TOTAL>>>(1, S_SZ & 1, -1, 0, x, outW);
    // decoder steps 1..95: feedback folded into weights (set 2)
    for (int t = 1; t < F_SZ; t++)
        step_kernel<<<grid, 512, SMEM_TOTAL>>>(2, (S_SZ + t) & 1, -1, t, x, outW);

    out_kernel<<<(B_SZ * F_SZ + 255) / 256, 256>>>((float*)d_out, outB);
}

// round 12
// speedup vs baseline: 1.2785x; 1.2785x over previous
#include <cuda_runtime.h>
#include <cuda_fp16.h>
#include <cuda_bf16.h>
#include <cstdint>

// ---------------- problem dims ----------------
#define B_SZ   1024
#define S_SZ   256
#define IN_SZ  8
#define H_SZ   512
#define F_SZ   96
#define G4     2048          // 4*H
#define KV     1024          // virtual K: [Ah | Ah] x [Wh | Wl]  (fp16 2-term split)
#define NCHUNK 16            // KV / 64
#define NCTA_N 16
#define NCTA_M 8

// ---------------- shared memory layout ----------------
// 4 stages x (A 16 KB + B 16 KB); epilogue reuses stage region as C (128x132 f32)
#define STAGE_BYTES 32768
#define SM_BIAS   131072
#define SM_WIH    131584
#define SM_XS     135680
#define SM_OUTW   140288
#define SMEM_TOTAL 140416

// ---------------- static device scratch (no runtime alloc) ----------------
__device__ __align__(1024) __half g_Wv[3][(size_t)G4 * KV];   // enc / dec0 / dec-folded
__device__ __align__(1024) __half g_A[2][(size_t)B_SZ * KV];  // ping-pong A_virt
__device__ __align__(1024) float g_Cst[B_SZ * H_SZ];          // cell state fp32
__device__ float g_bias[3][G4];                               // permuted fused biases
__device__ float g_WihP[G4 * IN_SZ];                          // permuted enc_Wih
__device__ float g_predP[F_SZ][NCTA_N][B_SZ];                 // per-nCTA pred partials

// ---------------- helpers ----------------
__device__ __forceinline__ uint32_t smem_u32(const void* p) {
    uint32_t a;
    asm("{ .reg .u64 t; cvta.to.shared.u64 t, %1; cvt.u32.u64 %0, t; }" : "=r"(a) : "l"(p));
    return a;
}
__device__ __forceinline__ void cp16(uint32_t saddr, const void* gptr) {
    asm volatile("cp.async.cg.shared.global [%0], [%1], 16;"
                 :: "r"(saddr), "l"(__cvta_generic_to_global(gptr)) : "memory");
}
#define CP_COMMIT() asm volatile("cp.async.commit_group;" ::: "memory")
#define CP_WAIT2()  asm volatile("cp.async.wait_group 2;" ::: "memory")
#define CP_WAIT0()  asm volatile("cp.async.wait_group 0;" ::: "memory")

__device__ __forceinline__ void ldm4(uint32_t& r0, uint32_t& r1, uint32_t& r2, uint32_t& r3,
                                     uint32_t addr) {
    asm volatile("ldmatrix.sync.aligned.m8n8.x4.shared.b16 {%0,%1,%2,%3}, [%4];"
                 : "=r"(r0), "=r"(r1), "=r"(r2), "=r"(r3) : "r"(addr));
}
__device__ __forceinline__ void mma16816(float* c, const uint32_t* a, const uint32_t* b) {
    asm volatile(
        "mma.sync.aligned.m16n8k16.row.col.f32.f16.f16.f32 "
        "{%0,%1,%2,%3}, {%4,%5,%6,%7}, {%8,%9}, {%0,%1,%2,%3};"
        : "+f"(c[0]), "+f"(c[1]), "+f"(c[2]), "+f"(c[3])
        : "r"(a[0]), "r"(a[1]), "r"(a[2]), "r"(a[3]), "r"(b[0]), "r"(b[1]));
}

// ---------------- prep: permute + fp16 hi/lo split weights, fold decoder feedback ----------------
// permuted col p = 4u + gate  <-  source row s = gate*512 + u  (PyTorch gate order i,f,g,o)
__global__ void prep_kernel(const float* __restrict__ encWhh, const float* __restrict__ decWhh,
                            const float* __restrict__ decWih, const float* __restrict__ outW,
                            const float* __restrict__ encBih, const float* __restrict__ encBhh,
                            const float* __restrict__ decBih, const float* __restrict__ decBhh,
                            const float* __restrict__ outB,   const float* __restrict__ encWih) {
    int idx = blockIdx.x * blockDim.x + threadIdx.x;
    if (idx < G4 * H_SZ) {
        int p = idx >> 9;
        int k = idx & 511;
        int s = ((p & 3) << 9) | (p >> 2);
        size_t o = (size_t)p * KV + k;

        float v0 = encWhh[s * H_SZ + k];
        __half h0 = __float2half_rn(v0);
        g_Wv[0][o] = h0; g_Wv[0][o + 512] = __float2half_rn(v0 - __half2float(h0));

        float v1 = decWhh[s * H_SZ + k];
        __half h1 = __float2half_rn(v1);
        g_Wv[1][o] = h1; g_Wv[1][o + 512] = __float2half_rn(v1 - __half2float(h1));

        float v2 = v1 + decWih[s] * outW[k];           // fold y-feedback into Whh
        __half h2 = __float2half_rn(v2);
        g_Wv[2][o] = h2; g_Wv[2][o + 512] = __float2half_rn(v2 - __half2float(h2));
    }
    if (idx < G4) {
        int p = idx;
        int s = ((p & 3) << 9) | (p >> 2);
        g_bias[0][p] = encBih[s] + encBhh[s];
        float db = decBih[s] + decBhh[s];
        g_bias[1][p] = db;
        g_bias[2][p] = db + outB[0] * decWih[s];       // fold outB feedback
#pragma unroll
        for (int j = 0; j < IN_SZ; j++) g_WihP[p * IN_SZ + j] = encWih[s * IN_SZ + j];
    }
}

__global__ void init_kernel() {
    int i = blockIdx.x * blockDim.x + threadIdx.x;
    int stride = gridDim.x * blockDim.x;
    uint32_t* a0 = reinterpret_cast<uint32_t*>(g_A[0]);
    for (int idx = i; idx < B_SZ * KV / 2; idx += stride) a0[idx] = 0u;
    for (int idx = i; idx < B_SZ * H_SZ; idx += stride) g_Cst[idx] = 0.f;
}

// ---------------- one LSTM time step ----------------
// C[128x128 tile] = A_virt[1024x1024] x B_virt[2048x1024]^T, then gate math locally.
// grid (16, 8): blockIdx.x = N-tile (128 permuted gate cols = 32 units), blockIdx.y = M-tile.
// 256 threads = 8 warps arranged 2m x 2n x 2k; warp tile 64m x 64n; each warp does 2 of
// the 4 k16-slices per chunk; k-halves reduced through smem at spill time.
// Fragments software-pipelined: slice j+1 LDSMs issue under slice j's 32 MMAs.
__global__ void __launch_bounds__(256, 1)
step_kernel(int wsel, int pb, int t_x, int td,
            const float* __restrict__ x, const float* __restrict__ outW) {
    extern __shared__ char smem[];
    const uint32_t sb = smem_u32(smem);
    const int tid = threadIdx.x;
    const int n0 = blockIdx.x, m0 = blockIdx.y;
    const bool has_x = (t_x >= 0);

    // ---- epilogue constants into their own smem region ----
    float* sm_bias = (float*)(smem + SM_BIAS);
    float* sm_wih  = (float*)(smem + SM_WIH);
    float* sm_xs   = (float*)(smem + SM_XS);
    float* sm_outw = (float*)(smem + SM_OUTW);
    if (tid < 128) sm_bias[tid] = g_bias[wsel][n0 * 128 + tid];
    if (tid < 32)  sm_outw[tid] = outW[n0 * 32 + tid];
    if (has_x) {
        for (int i = tid; i < 128 * IN_SZ; i += 256) {
            sm_wih[i] = g_WihP[n0 * 128 * IN_SZ + i];
            int r = i >> 3, j = i & 7;
            sm_xs[r * 9 + j] = x[((size_t)(m0 * 128 + r) * S_SZ + t_x) * IN_SZ + j];
        }
    }

    const __half* __restrict__ gA = g_A[pb] + (size_t)m0 * 128 * KV;
    const __half* __restrict__ gB = g_Wv[wsel] + (size_t)n0 * 128 * KV;

    // ---- stage loader: global -> XOR-swizzled smem via cp.async (256 threads) ----
    auto load_stage = [&](int kc, int slot) {
        const uint32_t stA = sb + slot * STAGE_BYTES;
        const uint32_t stB = stA + 16384;
        const int c16 = tid & 7;
        const int rb = tid >> 3;          // 0..31
#pragma unroll
        for (int it = 0; it < 4; it++) {
            int r = rb + it * 32;
            uint32_t so = (uint32_t)(r * 128 + ((c16 ^ (r & 7)) << 4));
            cp16(stA + so, gA + (size_t)r * KV + kc * 64 + c16 * 8);
            cp16(stB + so, gB + (size_t)r * KV + kc * 64 + c16 * 8);
        }
    };

    load_stage(0, 0); CP_COMMIT();
    load_stage(1, 1); CP_COMMIT();
    load_stage(2, 2); CP_COMMIT();

    const int lane = tid & 31, w = tid >> 5;
    const int wk = w & 1;                 // K-half of each chunk (slices wk*2, wk*2+1)
    const int wn = (w >> 1) & 1;          // 2 n-columns of 64
    const int wm = w >> 2;                // 2 m-rows of 64
    const int lrow = lane & 15, lhalf = lane >> 4;

    float acc[4][8][4];
#pragma unroll
    for (int a = 0; a < 4; a++)
#pragma unroll
        for (int b = 0; b < 8; b++)
#pragma unroll
            for (int c = 0; c < 4; c++) acc[a][b][c] = 0.f;

    // ---- mainloop: 16 chunks of K=64, 4-stage cp.async pipeline, warp K-split ----
    for (int kc = 0; kc < NCHUNK; kc++) {
        CP_WAIT2();
        __syncthreads();
        const uint32_t stA = sb + (kc & 3) * STAGE_BYTES;
        const uint32_t stB = stA + 16384;

        uint32_t af[2][4][4], bf[2][8][2];
        // load fragments for slice set j (k16-slice s = wk*2 + j)
#pragma unroll
        for (int j = 0; j < 2; j++) {
            const int c16 = 2 * (wk * 2 + j) + lhalf;
#pragma unroll
            for (int mt = 0; mt < 4; mt++) {
                int r = wm * 64 + mt * 16 + lrow;
                ldm4(af[j][mt][0], af[j][mt][1], af[j][mt][2], af[j][mt][3],
                     stA + r * 128 + ((c16 ^ (r & 7)) << 4));
            }
#pragma unroll
            for (int nb = 0; nb < 4; nb++) {
                int r = wn * 64 + nb * 16 + lrow;
                uint32_t r0, r1, r2, r3;
                ldm4(r0, r1, r2, r3, stB + r * 128 + ((c16 ^ (r & 7)) << 4));
                bf[j][nb * 2 + 0][0] = r0; bf[j][nb * 2 + 0][1] = r2;
                bf[j][nb * 2 + 1][0] = r1; bf[j][nb * 2 + 1][1] = r3;
            }
            if (j == 0) {
                // slice-0 MMAs overlap slice-1 LDSMs (next unroll iteration issues them
                // after these mmas in program order, but mmas depend only on set 0)
                continue;
            }
        }
        // MMA slice 0
#pragma unroll
        for (int mt = 0; mt < 4; mt++)
#pragma unroll
            for (int nt = 0; nt < 8; nt++)
                mma16816(acc[mt][nt], af[0][mt], bf[0][nt]);
        // issue next-chunk loads between the two MMA blocks
        if (kc + 3 < NCHUNK) load_stage(kc + 3, (kc + 3) & 3);
        CP_COMMIT();   // unconditional: keeps wait_group 2 semantics at the tail
        // MMA slice 1
#pragma unroll
        for (int mt = 0; mt < 4; mt++)
#pragma unroll
            for (int nt = 0; nt < 8; nt++)
                mma16816(acc[mt][nt], af[1][mt], bf[1][nt]);
    }
    CP_WAIT0();        // drain empty tail groups before smem reuse

    // ---- spill + K-half reduction into smem C tile (stride 132, aligned float2) ----
    __syncthreads();
    float* Cs = reinterpret_cast<float*>(smem);
    if (wk == 0) {
#pragma unroll
        for (int mt = 0; mt < 4; mt++) {
#pragma unroll
            for (int nt = 0; nt < 8; nt++) {
                int r = wm * 64 + mt * 16 + (lane >> 2);
                int c = wn * 64 + nt * 8 + 2 * (lane & 3);
                Cs[r * 132 + c]           = acc[mt][nt][0];
                Cs[r * 132 + c + 1]       = acc[mt][nt][1];
                Cs[(r + 8) * 132 + c]     = acc[mt][nt][2];
                Cs[(r + 8) * 132 + c + 1] = acc[mt][nt][3];
            }
        }
    }
    __syncthreads();
    if (wk == 1) {
#pragma unroll
        for (int mt = 0; mt < 4; mt++) {
#pragma unroll
            for (int nt = 0; nt < 8; nt++) {
                int r = wm * 64 + mt * 16 + (lane >> 2);
                int c = wn * 64 + nt * 8 + 2 * (lane & 3);
                float2* p0 = reinterpret_cast<float2*>(&Cs[r * 132 + c]);
                float2 v0 = *p0; v0.x += acc[mt][nt][0]; v0.y += acc[mt][nt][1]; *p0 = v0;
                float2* p1 = reinterpret_cast<float2*>(&Cs[(r + 8) * 132 + c]);
                float2 v1 = *p1; v1.x += acc[mt][nt][2]; v1.y += acc[mt][nt][3]; *p1 = v1;
            }
        }
    }
    __syncthreads();

    // ---- gate pass: lane = local unit (cols 4u..4u+3 = i,f,g,o), 8 warps x 16 rows ----
    const int u = lane;
    const int ug = n0 * 32 + u;
    float wih[4][8];
    if (has_x) {
#pragma unroll
        for (int q = 0; q < 4; q++)
#pragma unroll
            for (int k = 0; k < 8; k++) wih[q][k] = sm_wih[(4 * u + q) * 8 + k];
    }
    const float b_i = sm_bias[4 * u], b_f = sm_bias[4 * u + 1];
    const float b_g = sm_bias[4 * u + 2], b_o = sm_bias[4 * u + 3];
    const float ow = sm_outw[u];
    __half* __restrict__ hout = g_A[pb ^ 1];

#pragma unroll 4
    for (int i = 0; i < 16; i++) {
        int r = w + i * 8;
        int grow = m0 * 128 + r;
        const float4 g4v = *reinterpret_cast<const float4*>(&Cs[r * 132 + 4 * u]);
        float gi = g4v.x + b_i, gf = g4v.y + b_f, gg = g4v.z + b_g, go = g4v.w + b_o;
        if (has_x) {
#pragma unroll
            for (int k = 0; k < 8; k++) {
                float xv = sm_xs[r * 9 + k];
                gi += xv * wih[0][k]; gf += xv * wih[1][k];
                gg += xv * wih[2][k]; go += xv * wih[3][k];
            }
        }
        float iv = 1.f / (1.f + expf(-gi));
        float fv = 1.f / (1.f + expf(-gf));
        float gv = tanhf(gg);
        float ov = 1.f / (1.f + expf(-go));
        size_t ci = (size_t)grow * H_SZ + ug;
        float cn = fv * g_Cst[ci] + iv * gv;
        g_Cst[ci] = cn;
        float hv = ov * tanhf(cn);
        __half hh = __float2half_rn(hv);
        __half* rowp = hout + (size_t)grow * KV;
        rowp[ug] = hh; rowp[512 + ug] = hh;            // A_virt = [Ah | Ah]
        if (td >= 0) {
            float p = hv * ow;
#pragma unroll
            for (int s = 16; s > 0; s >>= 1) p += __shfl_xor_sync(0xFFFFFFFFu, p, s);
            if (lane == 0) g_predP[td][n0][grow] = p;   // deterministic partial
        }
    }
}

// ---------------- output: out[b][f] = outB + sum_n predP[f][n][b] ----------------
__global__ void out_kernel(float* __restrict__ out, const float* __restrict__ outB) {
    int i = blockIdx.x * blockDim.x + threadIdx.x;
    if (i < B_SZ * F_SZ) {
        int b = i / F_SZ, f = i % F_SZ;
        float s = outB[0];
#pragma unroll
        for (int n = 0; n < NCTA_N; n++) s += g_predP[f][n][b];
        out[i] = s;
    }
}

// ---------------- launch ----------------
extern "C" void kernel_launch(void* const* d_in, const int* in_sizes, int n_in,
                              void* d_out, int out_size) {
    const float* x      = (const float*)d_in[0];
    const float* encWih = (const float*)d_in[1];
    const float* encWhh = (const float*)d_in[2];
    const float* encBih = (const float*)d_in[3];
    const float* encBhh = (const float*)d_in[4];
    const float* decWih = (const float*)d_in[5];
    const float* decWhh = (const float*)d_in[6];
    const float* decBih = (const float*)d_in[7];
    const float* decBhh = (const float*)d_in[8];
    const float* outW   = (const float*)d_in[9];
    const float* outB   = (const float*)d_in[10];

    cudaFuncSetAttribute(step_kernel, cudaFuncAttributeMaxDynamicSharedMemorySize, SMEM_TOTAL);

    init_kernel<<<512, 256>>>();
    prep_kernel<<<(G4 * H_SZ + 255) / 256, 256>>>(encWhh, decWhh, decWih, outW,
                                                  encBih, encBhh, decBih, decBhh, outB, encWih);
    dim3 grid(NCTA_N, NCTA_M);
    // encoder: 256 steps with x-term, weight set 0
    for (int t = 0; t < S_SZ; t++)
        step_kernel<<<grid, 256, SMEM_TOTAL>>>(0, t & 1, t, -1, x, outW);
    // decoder step 0: y0 = 0 -> plain dec weights (set 1)
    step_kernel<<<grid, 256, SMEM_TOTAL>>>(1, S_SZ & 1, -1, 0, x, outW);
    // decoder steps 1..95: feedback folded into weights (set 2)
    for (int t = 1; t < F_SZ; t++)
        step_kernel<<<grid, 256, SMEM_TOTAL>>>(2, (S_SZ + t) & 1, -1, t, x, outW);

    out_kernel<<<(B_SZ * F_SZ + 255) / 256, 256>>>((float*)d_out, outB);
}

// round 14
// speedup vs baseline: 2.0186x; 1.5789x over previous
#include <cuda_runtime.h>
#include <cuda_fp16.h>
#include <cuda_bf16.h>
#include <cstdint>

// ---------------- problem dims ----------------
#define B_SZ   1024
#define S_SZ   256
#define IN_SZ  8
#define H_SZ   512
#define F_SZ   96
#define G4     2048          // 4*H
#define KV     512           // single-pass fp16: A = [Ah], B = [Wh]
#define NCHUNK 8             // KV / 64
#define NCTA_N 16
#define NCTA_M 8

// ---------------- shared memory layout ----------------
// 4 stages x (A 16 KB + B 16 KB); epilogue reuses stage region as C (128x132 f32)
#define STAGE_BYTES 32768
#define SM_BIAS   131072
#define SM_WIH    131584
#define SM_XS     135680
#define SM_OUTW   140288
#define SMEM_TOTAL 140416

// ---------------- static device scratch (no runtime alloc) ----------------
__device__ __align__(1024) __half g_Wv[3][(size_t)G4 * KV];   // enc / dec0 / dec-folded
__device__ __align__(1024) __half g_A[2][(size_t)B_SZ * KV];  // ping-pong h (fp16)
__device__ __align__(1024) float g_Cst[B_SZ * H_SZ];          // cell state fp32
__device__ float g_bias[3][G4];                               // permuted fused biases
__device__ float g_WihP[G4 * IN_SZ];                          // permuted enc_Wih
__device__ float g_predP[F_SZ][NCTA_N][B_SZ];                 // per-nCTA pred partials

// ---------------- helpers ----------------
__device__ __forceinline__ uint32_t smem_u32(const void* p) {
    uint32_t a;
    asm("{ .reg .u64 t; cvta.to.shared.u64 t, %1; cvt.u32.u64 %0, t; }" : "=r"(a) : "l"(p));
    return a;
}
__device__ __forceinline__ void cp16(uint32_t saddr, const void* gptr) {
    asm volatile("cp.async.cg.shared.global [%0], [%1], 16;"
                 :: "r"(saddr), "l"(__cvta_generic_to_global(gptr)) : "memory");
}
#define CP_COMMIT() asm volatile("cp.async.commit_group;" ::: "memory")
#define CP_WAIT2()  asm volatile("cp.async.wait_group 2;" ::: "memory")
#define CP_WAIT0()  asm volatile("cp.async.wait_group 0;" ::: "memory")

__device__ __forceinline__ void ldm4(uint32_t& r0, uint32_t& r1, uint32_t& r2, uint32_t& r3,
                                     uint32_t addr) {
    asm volatile("ldmatrix.sync.aligned.m8n8.x4.shared.b16 {%0,%1,%2,%3}, [%4];"
                 : "=r"(r0), "=r"(r1), "=r"(r2), "=r"(r3) : "r"(addr));
}
__device__ __forceinline__ void mma16816(float* c, const uint32_t* a, const uint32_t* b) {
    asm volatile(
        "mma.sync.aligned.m16n8k16.row.col.f32.f16.f16.f32 "
        "{%0,%1,%2,%3}, {%4,%5,%6,%7}, {%8,%9}, {%0,%1,%2,%3};"
        : "+f"(c[0]), "+f"(c[1]), "+f"(c[2]), "+f"(c[3])
        : "r"(a[0]), "r"(a[1]), "r"(a[2]), "r"(a[3]), "r"(b[0]), "r"(b[1]));
}

// ---------------- prep: permute weights to fp16, fold decoder feedback ----------------
// permuted col p = 4u + gate  <-  source row s = gate*512 + u  (PyTorch gate order i,f,g,o)
__global__ void prep_kernel(const float* __restrict__ encWhh, const float* __restrict__ decWhh,
                            const float* __restrict__ decWih, const float* __restrict__ outW,
                            const float* __restrict__ encBih, const float* __restrict__ encBhh,
                            const float* __restrict__ decBih, const float* __restrict__ decBhh,
                            const float* __restrict__ outB,   const float* __restrict__ encWih) {
    int idx = blockIdx.x * blockDim.x + threadIdx.x;
    if (idx < G4 * H_SZ) {
        int p = idx >> 9;
        int k = idx & 511;
        int s = ((p & 3) << 9) | (p >> 2);
        size_t o = (size_t)p * KV + k;

        g_Wv[0][o] = __float2half_rn(encWhh[s * H_SZ + k]);
        float v1 = decWhh[s * H_SZ + k];
        g_Wv[1][o] = __float2half_rn(v1);
        g_Wv[2][o] = __float2half_rn(v1 + decWih[s] * outW[k]);   // fold y-feedback
    }
    if (idx < G4) {
        int p = idx;
        int s = ((p & 3) << 9) | (p >> 2);
        g_bias[0][p] = encBih[s] + encBhh[s];
        float db = decBih[s] + decBhh[s];
        g_bias[1][p] = db;
        g_bias[2][p] = db + outB[0] * decWih[s];       // fold outB feedback
#pragma unroll
        for (int j = 0; j < IN_SZ; j++) g_WihP[p * IN_SZ + j] = encWih[s * IN_SZ + j];
    }
}

__global__ void init_kernel() {
    int i = blockIdx.x * blockDim.x + threadIdx.x;
    int stride = gridDim.x * blockDim.x;
    uint32_t* a0 = reinterpret_cast<uint32_t*>(g_A[0]);
    for (int idx = i; idx < B_SZ * KV / 2; idx += stride) a0[idx] = 0u;
    for (int idx = i; idx < B_SZ * H_SZ; idx += stride) g_Cst[idx] = 0.f;
}

// ---------------- one LSTM time step ----------------
// C[128x128 tile] = A[1024x512] x B[2048x512]^T, then gate math locally.
// grid (16, 8): blockIdx.x = N-tile (128 permuted gate cols = 32 units), blockIdx.y = M-tile.
// 512 threads = 16 warps arranged 2m x 4n x 2k; warp tile 64m x 32n; K-chunk halves
// reduced through smem at spill time.
__global__ void __launch_bounds__(512, 1)
step_kernel(int wsel, int pb, int t_x, int td,
            const float* __restrict__ x, const float* __restrict__ outW) {
    extern __shared__ char smem[];
    const uint32_t sb = smem_u32(smem);
    const int tid = threadIdx.x;
    const int n0 = blockIdx.x, m0 = blockIdx.y;
    const bool has_x = (t_x >= 0);

    // ---- epilogue constants into their own smem region ----
    float* sm_bias = (float*)(smem + SM_BIAS);
    float* sm_wih  = (float*)(smem + SM_WIH);
    float* sm_xs   = (float*)(smem + SM_XS);
    float* sm_outw = (float*)(smem + SM_OUTW);
    if (tid < 128) sm_bias[tid] = g_bias[wsel][n0 * 128 + tid];
    if (tid < 32)  sm_outw[tid] = outW[n0 * 32 + tid];
    if (has_x) {
        for (int i = tid; i < 128 * IN_SZ; i += 512) {
            sm_wih[i] = g_WihP[n0 * 128 * IN_SZ + i];
            int r = i >> 3, j = i & 7;
            sm_xs[r * 9 + j] = x[((size_t)(m0 * 128 + r) * S_SZ + t_x) * IN_SZ + j];
        }
    }

    const __half* __restrict__ gA = g_A[pb] + (size_t)m0 * 128 * KV;
    const __half* __restrict__ gB = g_Wv[wsel] + (size_t)n0 * 128 * KV;

    // ---- stage loader: global -> XOR-swizzled smem via cp.async (512 threads) ----
    auto load_stage = [&](int kc, int slot) {
        const uint32_t stA = sb + slot * STAGE_BYTES;
        const uint32_t stB = stA + 16384;
        const int c16 = tid & 7;
        const int rb = tid >> 3;          // 0..63
#pragma unroll
        for (int it = 0; it < 2; it++) {
            int r = rb + it * 64;
            uint32_t so = (uint32_t)(r * 128 + ((c16 ^ (r & 7)) << 4));
            cp16(stA + so, gA + (size_t)r * KV + kc * 64 + c16 * 8);
            cp16(stB + so, gB + (size_t)r * KV + kc * 64 + c16 * 8);
        }
    };

    load_stage(0, 0); CP_COMMIT();
    load_stage(1, 1); CP_COMMIT();
    load_stage(2, 2); CP_COMMIT();

    const int lane = tid & 31, w = tid >> 5;
    const int wk = w & 1;                 // K-half of each chunk
    const int wn = (w >> 1) & 3;          // 4 n-columns of 32
    const int wm = w >> 3;                // 2 m-rows of 64
    const int lrow = lane & 15, lhalf = lane >> 4;

    float acc[4][4][4];
#pragma unroll
    for (int a = 0; a < 4; a++)
#pragma unroll
        for (int b = 0; b < 4; b++)
#pragma unroll
            for (int c = 0; c < 4; c++) acc[a][b][c] = 0.f;

    // ---- mainloop: 8 chunks of K=64, 4-stage cp.async pipeline, warp K-split ----
    for (int kc = 0; kc < NCHUNK; kc++) {
        CP_WAIT2();
        __syncthreads();
        const uint32_t stA = sb + (kc & 3) * STAGE_BYTES;
        const uint32_t stB = stA + 16384;
#pragma unroll
        for (int j = 0; j < 2; j++) {
            const int c16 = 2 * (wk * 2 + j) + lhalf;
            uint32_t af[4][4];
#pragma unroll
            for (int mt = 0; mt < 4; mt++) {
                int r = wm * 64 + mt * 16 + lrow;
                ldm4(af[mt][0], af[mt][1], af[mt][2], af[mt][3],
                     stA + r * 128 + ((c16 ^ (r & 7)) << 4));
            }
            uint32_t bfr[4][2];
#pragma unroll
            for (int nb = 0; nb < 2; nb++) {
                int r = wn * 32 + nb * 16 + lrow;
                uint32_t r0, r1, r2, r3;
                ldm4(r0, r1, r2, r3, stB + r * 128 + ((c16 ^ (r & 7)) << 4));
                bfr[nb * 2 + 0][0] = r0; bfr[nb * 2 + 0][1] = r2;
                bfr[nb * 2 + 1][0] = r1; bfr[nb * 2 + 1][1] = r3;
            }
#pragma unroll
            for (int mt = 0; mt < 4; mt++)
#pragma unroll
                for (int nt = 0; nt < 4; nt++)
                    mma16816(acc[mt][nt], af[mt], bfr[nt]);
        }
        if (kc + 3 < NCHUNK) load_stage(kc + 3, (kc + 3) & 3);
        CP_COMMIT();   // unconditional: keeps wait_group 2 semantics at the tail
    }
    CP_WAIT0();        // drain empty tail groups before smem reuse

    // ---- spill + K-half reduction into smem C tile (stride 132, aligned float2) ----
    __syncthreads();
    float* Cs = reinterpret_cast<float*>(smem);
    if (wk == 0) {
#pragma unroll
        for (int mt = 0; mt < 4; mt++) {
#pragma unroll
            for (int nt = 0; nt < 4; nt++) {
                int r = wm * 64 + mt * 16 + (lane >> 2);
                int c = wn * 32 + nt * 8 + 2 * (lane & 3);
                Cs[r * 132 + c]           = acc[mt][nt][0];
                Cs[r * 132 + c + 1]       = acc[mt][nt][1];
                Cs[(r + 8) * 132 + c]     = acc[mt][nt][2];
                Cs[(r + 8) * 132 + c + 1] = acc[mt][nt][3];
            }
        }
    }
    __syncthreads();
    if (wk == 1) {
#pragma unroll
        for (int mt = 0; mt < 4; mt++) {
#pragma unroll
            for (int nt = 0; nt < 4; nt++) {
                int r = wm * 64 + mt * 16 + (lane >> 2);
                int c = wn * 32 + nt * 8 + 2 * (lane & 3);
                float2* p0 = reinterpret_cast<float2*>(&Cs[r * 132 + c]);
                float2 v0 = *p0; v0.x += acc[mt][nt][0]; v0.y += acc[mt][nt][1]; *p0 = v0;
                float2* p1 = reinterpret_cast<float2*>(&Cs[(r + 8) * 132 + c]);
                float2 v1 = *p1; v1.x += acc[mt][nt][2]; v1.y += acc[mt][nt][3]; *p1 = v1;
            }
        }
    }
    __syncthreads();

    // ---- gate pass: lane = local unit (cols 4u..4u+3 = i,f,g,o), 16 warps x 8 rows ----
    const int u = lane;
    const int ug = n0 * 32 + u;
    float wih[4][8];
    if (has_x) {
#pragma unroll
        for (int q = 0; q < 4; q++)
#pragma unroll
            for (int k = 0; k < 8; k++) wih[q][k] = sm_wih[(4 * u + q) * 8 + k];
    }
    const float b_i = sm_bias[4 * u], b_f = sm_bias[4 * u + 1];
    const float b_g = sm_bias[4 * u + 2], b_o = sm_bias[4 * u + 3];
    const float ow = sm_outw[u];
    __half* __restrict__ hout = g_A[pb ^ 1];
    const int wrow = tid >> 5;

#pragma unroll 4
    for (int i = 0; i < 8; i++) {
        int r = wrow + i * 16;
        int grow = m0 * 128 + r;
        const float4 g4v = *reinterpret_cast<const float4*>(&Cs[r * 132 + 4 * u]);
        float gi = g4v.x + b_i, gf = g4v.y + b_f, gg = g4v.z + b_g, go = g4v.w + b_o;
        if (has_x) {
#pragma unroll
            for (int k = 0; k < 8; k++) {
                float xv = sm_xs[r * 9 + k];
                gi += xv * wih[0][k]; gf += xv * wih[1][k];
                gg += xv * wih[2][k]; go += xv * wih[3][k];
            }
        }
        float iv = 1.f / (1.f + expf(-gi));
        float fv = 1.f / (1.f + expf(-gf));
        float gv = tanhf(gg);
        float ov = 1.f / (1.f + expf(-go));
        size_t ci = (size_t)grow * H_SZ + ug;
        float cn = fv * g_Cst[ci] + iv * gv;
        g_Cst[ci] = cn;
        float hv = ov * tanhf(cn);
        hout[(size_t)grow * KV + ug] = __float2half_rn(hv);
        if (td >= 0) {
            float p = hv * ow;
#pragma unroll
            for (int s = 16; s > 0; s >>= 1) p += __shfl_xor_sync(0xFFFFFFFFu, p, s);
            if (lane == 0) g_predP[td][n0][grow] = p;   // deterministic partial
        }
    }
}

// ---------------- output: out[b][f] = outB + sum_n predP[f][n][b] ----------------
__global__ void out_kernel(float* __restrict__ out, const float* __restrict__ outB) {
    int i = blockIdx.x * blockDim.x + threadIdx.x;
    if (i < B_SZ * F_SZ) {
        int b = i / F_SZ, f = i % F_SZ;
        float s = outB[0];
#pragma unroll
        for (int n = 0; n < NCTA_N; n++) s += g_predP[f][n][b];
        out[i] = s;
    }
}

// ---------------- launch ----------------
extern "C" void kernel_launch(void* const* d_in, const int* in_sizes, int n_in,
                              void* d_out, int out_size) {
    const float* x      = (const float*)d_in[0];
    const float* encWih = (const float*)d_in[1];
    const float* encWhh = (const float*)d_in[2];
    const float* encBih = (const float*)d_in[3];
    const float* encBhh = (const float*)d_in[4];
    const float* decWih = (const float*)d_in[5];
    const float* decWhh = (const float*)d_in[6];
    const float* decBih = (const float*)d_in[7];
    const float* decBhh = (const float*)d_in[8];
    const float* outW   = (const float*)d_in[9];
    const float* outB   = (const float*)d_in[10];

    cudaFuncSetAttribute(step_kernel, cudaFuncAttributeMaxDynamicSharedMemorySize, SMEM_TOTAL);

    init_kernel<<<512, 256>>>();
    prep_kernel<<<(G4 * H_SZ + 255) / 256, 256>>>(encWhh, decWhh, decWih, outW,
                                                  encBih, encBhh, decBih, decBhh, outB, encWih);
    dim3 grid(NCTA_N, NCTA_M);
    // encoder: 256 steps with x-term, weight set 0
    for (int t = 0; t < S_SZ; t++)
        step_kernel<<<grid, 512, SMEM_TOTAL>>>(0, t & 1, t, -1, x, outW);
    // decoder step 0: y0 = 0 -> plain dec weights (set 1)
    step_kernel<<<grid, 512, SMEM_TOTAL>>>(1, S_SZ & 1, -1, 0, x, outW);
    // decoder steps 1..95: feedback folded into weights (set 2)
    for (int t = 1; t < F_SZ; t++)
        step_kernel<<<grid, 512, SMEM_TOTAL>>>(2, (S_SZ + t) & 1, -1, t, x, outW);

    out_kernel<<<(B_SZ * F_SZ + 255) / 256, 256>>>((float*)d_out, outB);
}

// round 15
// speedup vs baseline: 2.2656x; 1.1223x over previous
#include <cuda_runtime.h>
#include <cuda_fp16.h>
#include <cuda_bf16.h>
#include <cstdint>

// ---------------- problem dims ----------------
#define B_SZ   1024
#define S_SZ   256
#define IN_SZ  8
#define H_SZ   512
#define F_SZ   96
#define G4     2048          // 4*H
#define KV     512           // single-pass fp16: A = [Ah], B = [Wh]
#define NCHUNK 4             // KV / 128
#define NCTA_N 16
#define NCTA_M 8

// ---------------- shared memory layout ----------------
// 3 stages x 64 KB (A-sub0 16K | A-sub1 16K | B-sub0 16K | B-sub1 16K)
// epilogue reuses stage region as C (128x132 f32 = 67.6 KB)
#define STAGE_BYTES 65536
#define SM_BIAS   196608
#define SM_WIH    197120
#define SM_XS     201216
#define SM_OUTW   205824
#define SMEM_TOTAL 205952

// ---------------- static device scratch (no runtime alloc) ----------------
__device__ __align__(1024) __half g_Wv[3][(size_t)G4 * KV];   // enc / dec0 / dec-folded
__device__ __align__(1024) __half g_A[2][(size_t)B_SZ * KV];  // ping-pong h (fp16)
__device__ __align__(1024) float g_Cst[B_SZ * H_SZ];          // cell state fp32
__device__ float g_bias[3][G4];                               // permuted fused biases
__device__ float g_WihP[G4 * IN_SZ];                          // permuted enc_Wih
__device__ float g_predP[F_SZ][NCTA_N][B_SZ];                 // per-nCTA pred partials

// ---------------- helpers ----------------
__device__ __forceinline__ uint32_t smem_u32(const void* p) {
    uint32_t a;
    asm("{ .reg .u64 t; cvta.to.shared.u64 t, %1; cvt.u32.u64 %0, t; }" : "=r"(a) : "l"(p));
    return a;
}
__device__ __forceinline__ void cp16(uint32_t saddr, const void* gptr) {
    asm volatile("cp.async.cg.shared.global [%0], [%1], 16;"
                 :: "r"(saddr), "l"(__cvta_generic_to_global(gptr)) : "memory");
}
#define CP_COMMIT() asm volatile("cp.async.commit_group;" ::: "memory")
#define CP_WAIT1()  asm volatile("cp.async.wait_group 1;" ::: "memory")
#define CP_WAIT0()  asm volatile("cp.async.wait_group 0;" ::: "memory")

__device__ __forceinline__ void ldm4(uint32_t& r0, uint32_t& r1, uint32_t& r2, uint32_t& r3,
                                     uint32_t addr) {
    asm volatile("ldmatrix.sync.aligned.m8n8.x4.shared.b16 {%0,%1,%2,%3}, [%4];"
                 : "=r"(r0), "=r"(r1), "=r"(r2), "=r"(r3) : "r"(addr));
}
__device__ __forceinline__ void mma16816(float* c, const uint32_t* a, const uint32_t* b) {
    asm volatile(
        "mma.sync.aligned.m16n8k16.row.col.f32.f16.f16.f32 "
        "{%0,%1,%2,%3}, {%4,%5,%6,%7}, {%8,%9}, {%0,%1,%2,%3};"
        : "+f"(c[0]), "+f"(c[1]), "+f"(c[2]), "+f"(c[3])
        : "r"(a[0]), "r"(a[1]), "r"(a[2]), "r"(a[3]), "r"(b[0]), "r"(b[1]));
}

// fast activations: hardware EX2/RCP. Error ~2^-21 (far below fp16 h-quant 2^-11).
__device__ __forceinline__ float fsig(float x) {
    x = fminf(fmaxf(x, -30.f), 30.f);
    return __fdividef(1.f, 1.f + __expf(-x));
}
__device__ __forceinline__ float ftanh(float x) {
    x = fminf(fmaxf(x, -15.f), 15.f);
    float e = __expf(2.f * x);
    return __fdividef(e - 1.f, e + 1.f);
}

// ---------------- prep: permute weights to fp16, fold decoder feedback ----------------
// permuted col p = 4u + gate  <-  source row s = gate*512 + u  (PyTorch gate order i,f,g,o)
__global__ void prep_kernel(const float* __restrict__ encWhh, const float* __restrict__ decWhh,
                            const float* __restrict__ decWih, const float* __restrict__ outW,
                            const float* __restrict__ encBih, const float* __restrict__ encBhh,
                            const float* __restrict__ decBih, const float* __restrict__ decBhh,
                            const float* __restrict__ outB,   const float* __restrict__ encWih) {
    int idx = blockIdx.x * blockDim.x + threadIdx.x;
    if (idx < G4 * H_SZ) {
        int p = idx >> 9;
        int k = idx & 511;
        int s = ((p & 3) << 9) | (p >> 2);
        size_t o = (size_t)p * KV + k;

        g_Wv[0][o] = __float2half_rn(encWhh[s * H_SZ + k]);
        float v1 = decWhh[s * H_SZ + k];
        g_Wv[1][o] = __float2half_rn(v1);
        g_Wv[2][o] = __float2half_rn(v1 + decWih[s] * outW[k]);   // fold y-feedback
    }
    if (idx < G4) {
        int p = idx;
        int s = ((p & 3) << 9) | (p >> 2);
        g_bias[0][p] = encBih[s] + encBhh[s];
        float db = decBih[s] + decBhh[s];
        g_bias[1][p] = db;
        g_bias[2][p] = db + outB[0] * decWih[s];       // fold outB feedback
#pragma unroll
        for (int j = 0; j < IN_SZ; j++) g_WihP[p * IN_SZ + j] = encWih[s * IN_SZ + j];
    }
}

__global__ void init_kernel() {
    int i = blockIdx.x * blockDim.x + threadIdx.x;
    int stride = gridDim.x * blockDim.x;
    uint32_t* a0 = reinterpret_cast<uint32_t*>(g_A[0]);
    for (int idx = i; idx < B_SZ * KV / 2; idx += stride) a0[idx] = 0u;
    for (int idx = i; idx < B_SZ * H_SZ; idx += stride) g_Cst[idx] = 0.f;
}

// ---------------- one LSTM time step ----------------
// C[128x128 tile] = A[1024x512] x B[2048x512]^T, then gate math locally.
// grid (16, 8): blockIdx.x = N-tile (128 permuted gate cols = 32 units), blockIdx.y = M-tile.
// 512 threads = 16 warps arranged 2m x 4n x 2k; warp tile 64m x 32n; K-chunk = 128
// (two 64-K sub-blocks per stage); 3-stage cp.async pipeline; warp K-halves reduced
// through smem at spill time.
__global__ void __launch_bounds__(512, 1)
step_kernel(int wsel, int pb, int t_x, int td,
            const float* __restrict__ x, const float* __restrict__ outW) {
    extern __shared__ char smem[];
    const uint32_t sb = smem_u32(smem);
    const int tid = threadIdx.x;
    const int n0 = blockIdx.x, m0 = blockIdx.y;
    const bool has_x = (t_x >= 0);

    // ---- epilogue constants into their own smem region ----
    float* sm_bias = (float*)(smem + SM_BIAS);
    float* sm_wih  = (float*)(smem + SM_WIH);
    float* sm_xs   = (float*)(smem + SM_XS);
    float* sm_outw = (float*)(smem + SM_OUTW);
    if (tid < 128) sm_bias[tid] = g_bias[wsel][n0 * 128 + tid];
    if (tid < 32)  sm_outw[tid] = outW[n0 * 32 + tid];
    if (has_x) {
        for (int i = tid; i < 128 * IN_SZ; i += 512) {
            sm_wih[i] = g_WihP[n0 * 128 * IN_SZ + i];
            int r = i >> 3, j = i & 7;
            sm_xs[r * 9 + j] = x[((size_t)(m0 * 128 + r) * S_SZ + t_x) * IN_SZ + j];
        }
    }

    const __half* __restrict__ gA = g_A[pb] + (size_t)m0 * 128 * KV;
    const __half* __restrict__ gB = g_Wv[wsel] + (size_t)n0 * 128 * KV;

    // ---- stage loader: one K=128 chunk (4 x 16KB sub-blocks) via cp.async ----
    auto load_stage = [&](int kc, int slot) {
        const uint32_t st = sb + slot * STAGE_BYTES;
        const int c16 = tid & 7;
        const int rb = tid >> 3;          // 0..63
#pragma unroll
        for (int sub = 0; sub < 2; sub++) {
            const int kofs = kc * 128 + sub * 64;
#pragma unroll
            for (int it = 0; it < 2; it++) {
                int r = rb + it * 64;
                uint32_t so = (uint32_t)(r * 128 + ((c16 ^ (r & 7)) << 4));
                cp16(st + sub * 16384 + so,         gA + (size_t)r * KV + kofs + c16 * 8);
                cp16(st + 32768 + sub * 16384 + so, gB + (size_t)r * KV + kofs + c16 * 8);
            }
        }
    };

    load_stage(0, 0); CP_COMMIT();
    load_stage(1, 1); CP_COMMIT();

    const int lane = tid & 31, w = tid >> 5;
    const int wk = w & 1;                 // K-half of each chunk (64 K each)
    const int wn = (w >> 1) & 3;          // 4 n-columns of 32
    const int wm = w >> 3;                // 2 m-rows of 64
    const int lrow = lane & 15, lhalf = lane >> 4;

    float acc[4][4][4];
#pragma unroll
    for (int a = 0; a < 4; a++)
#pragma unroll
        for (int b = 0; b < 4; b++)
#pragma unroll
            for (int c = 0; c < 4; c++) acc[a][b][c] = 0.f;

    // ---- mainloop: 4 chunks of K=128, 3-stage pipeline, warp K-split ----
    for (int kc = 0; kc < NCHUNK; kc++) {
        CP_WAIT1();
        __syncthreads();
        const uint32_t st = sb + (kc % 3) * STAGE_BYTES;
#pragma unroll
        for (int j = 0; j < 4; j++) {
            const int s_g  = wk * 4 + j;          // global k16-slice 0..7
            const int sub  = s_g >> 2;
            const int c16  = 2 * (s_g & 3) + lhalf;
            const uint32_t stA = st + sub * 16384;
            const uint32_t stB = st + 32768 + sub * 16384;
            uint32_t af[4][4];
#pragma unroll
            for (int mt = 0; mt < 4; mt++) {
                int r = wm * 64 + mt * 16 + lrow;
                ldm4(af[mt][0], af[mt][1], af[mt][2], af[mt][3],
                     stA + r * 128 + ((c16 ^ (r & 7)) << 4));
            }
            uint32_t bfr[4][2];
#pragma unroll
            for (int nb = 0; nb < 2; nb++) {
                int r = wn * 32 + nb * 16 + lrow;
                uint32_t r0, r1, r2, r3;
                ldm4(r0, r1, r2, r3, stB + r * 128 + ((c16 ^ (r & 7)) << 4));
                bfr[nb * 2 + 0][0] = r0; bfr[nb * 2 + 0][1] = r2;
                bfr[nb * 2 + 1][0] = r1; bfr[nb * 2 + 1][1] = r3;
            }
#pragma unroll
            for (int mt = 0; mt < 4; mt++)
#pragma unroll
                for (int nt = 0; nt < 4; nt++)
                    mma16816(acc[mt][nt], af[mt], bfr[nt]);
        }
        __syncthreads();                           // all warps done with slot kc%3
        if (kc + 2 < NCHUNK) load_stage(kc + 2, (kc + 2) % 3);
        CP_COMMIT();   // unconditional: keeps wait_group 1 semantics at the tail
    }
    CP_WAIT0();        // drain before smem reuse

    // ---- spill + K-half reduction into smem C tile (stride 132, aligned float2) ----
    __syncthreads();
    float* Cs = reinterpret_cast<float*>(smem);
    if (wk == 0) {
#pragma unroll
        for (int mt = 0; mt < 4; mt++) {
#pragma unroll
            for (int nt = 0; nt < 4; nt++) {
                int r = wm * 64 + mt * 16 + (lane >> 2);
                int c = wn * 32 + nt * 8 + 2 * (lane & 3);
                Cs[r * 132 + c]           = acc[mt][nt][0];
                Cs[r * 132 + c + 1]       = acc[mt][nt][1];
                Cs[(r + 8) * 132 + c]     = acc[mt][nt][2];
                Cs[(r + 8) * 132 + c + 1] = acc[mt][nt][3];
            }
        }
    }
    __syncthreads();
    if (wk == 1) {
#pragma unroll
        for (int mt = 0; mt < 4; mt++) {
#pragma unroll
            for (int nt = 0; nt < 4; nt++) {
                int r = wm * 64 + mt * 16 + (lane >> 2);
                int c = wn * 32 + nt * 8 + 2 * (lane & 3);
                float2* p0 = reinterpret_cast<float2*>(&Cs[r * 132 + c]);
                float2 v0 = *p0; v0.x += acc[mt][nt][0]; v0.y += acc[mt][nt][1]; *p0 = v0;
                float2* p1 = reinterpret_cast<float2*>(&Cs[(r + 8) * 132 + c]);
                float2 v1 = *p1; v1.x += acc[mt][nt][2]; v1.y += acc[mt][nt][3]; *p1 = v1;
            }
        }
    }
    __syncthreads();

    // ---- gate pass: lane = local unit (cols 4u..4u+3 = i,f,g,o), 16 warps x 8 rows ----
    const int u = lane;
    const int ug = n0 * 32 + u;
    float wih[4][8];
    if (has_x) {
#pragma unroll
        for (int q = 0; q < 4; q++)
#pragma unroll
            for (int k = 0; k < 8; k++) wih[q][k] = sm_wih[(4 * u + q) * 8 + k];
    }
    const float b_i = sm_bias[4 * u], b_f = sm_bias[4 * u + 1];
    const float b_g = sm_bias[4 * u + 2], b_o = sm_bias[4 * u + 3];
    const float ow = sm_outw[u];
    __half* __restrict__ hout = g_A[pb ^ 1];
    const int wrow = tid >> 5;

#pragma unroll 4
    for (int i = 0; i < 8; i++) {
        int r = wrow + i * 16;
        int grow = m0 * 128 + r;
        const float4 g4v = *reinterpret_cast<const float4*>(&Cs[r * 132 + 4 * u]);
        float gi = g4v.x + b_i, gf = g4v.y + b_f, gg = g4v.z + b_g, go = g4v.w + b_o;
        if (has_x) {
#pragma unroll
            for (int k = 0; k < 8; k++) {
                float xv = sm_xs[r * 9 + k];
                gi += xv * wih[0][k]; gf += xv * wih[1][k];
                gg += xv * wih[2][k]; go += xv * wih[3][k];
            }
        }
        float iv = fsig(gi);
        float fv = fsig(gf);
        float gv = ftanh(gg);
        float ov = fsig(go);
        size_t ci = (size_t)grow * H_SZ + ug;
        float cn = fv * g_Cst[ci] + iv * gv;
        g_Cst[ci] = cn;
        float hv = ov * ftanh(cn);
        hout[(size_t)grow * KV + ug] = __float2half_rn(hv);
        if (td >= 0) {
            float p = hv * ow;
#pragma unroll
            for (int s = 16; s > 0; s >>= 1) p += __shfl_xor_sync(0xFFFFFFFFu, p, s);
            if (lane == 0) g_predP[td][n0][grow] = p;   // deterministic partial
        }
    }
}

// ---------------- output: out[b][f] = outB + sum_n predP[f][n][b] ----------------
__global__ void out_kernel(float* __restrict__ out, const float* __restrict__ outB) {
    int i = blockIdx.x * blockDim.x + threadIdx.x;
    if (i < B_SZ * F_SZ) {
        int b = i / F_SZ, f = i % F_SZ;
        float s = outB[0];
#pragma unroll
        for (int n = 0; n < NCTA_N; n++) s += g_predP[f][n][b];
        out[i] = s;
    }
}

// ---------------- launch ----------------
extern "C" void kernel_launch(void* const* d_in, const int* in_sizes, int n_in,
                              void* d_out, int out_size) {
    const float* x      = (const float*)d_in[0];
    const float* encWih = (const float*)d_in[1];
    const float* encWhh = (const float*)d_in[2];
    const float* encBih = (const float*)d_in[3];
    const float* encBhh = (const float*)d_in[4];
    const float* decWih = (const float*)d_in[5];
    const float* decWhh = (const float*)d_in[6];
    const float* decBih = (const float*)d_in[7];
    const float* decBhh = (const float*)d_in[8];
    const float* outW   = (const float*)d_in[9];
    const float* outB   = (const float*)d_in[10];

    cudaFuncSetAttribute(step_kernel, cudaFuncAttributeMaxDynamicSharedMemorySize, SMEM_TOTAL);

    init_kernel<<<512, 256>>>();
    prep_kernel<<<(G4 * H_SZ + 255) / 256, 256>>>(encWhh, decWhh, decWih, outW,
                                                  encBih, encBhh, decBih, decBhh, outB, encWih);
    dim3 grid(NCTA_N, NCTA_M);
    // encoder: 256 steps with x-term, weight set 0
    for (int t = 0; t < S_SZ; t++)
        step_kernel<<<grid, 512, SMEM_TOTAL>>>(0, t & 1, t, -1, x, outW);
    // decoder step 0: y0 = 0 -> plain dec weights (set 1)
    step_kernel<<<grid, 512, SMEM_TOTAL>>>(1, S_SZ & 1, -1, 0, x, outW);
    // decoder steps 1..95: feedback folded into weights (set 2)
    for (int t = 1; t < F_SZ; t++)
        step_kernel<<<grid, 512, SMEM_TOTAL>>>(2, (S_SZ + t) & 1, -1, t, x, outW);

    out_kernel<<<(B_SZ * F_SZ + 255) / 256, 256>>>((float*)d_out, outB);
}